// round 2
// baseline (speedup 1.0000x reference)
#include <cuda_runtime.h>
#include <cstdint>

#define BDIM 4
#define TDIM 2048
#define CDIM 1024
#define D6   (6 * CDIM)          // 6144
#define D2   (2 * CDIM)          // 2048
#define MROWS (BDIM * TDIM)      // 8192
#define CHUNK 64                 // T / 32 warps

// Scratch (allocation-free rule: __device__ globals)
__device__ float g_rkv[(size_t)MROWS * D6];   // [B*T, 6C]
__device__ float g_cat[(size_t)MROWS * D2];   // [B*T, 2C]

// ---------------------------------------------------------------------------
// GEMM (NT): C[M,N] = A[M,K] * B[N,K]^T, all row-major, K % 16 == 0,
// M % 128 == 0, N % 128 == 0. fp32 SIMT baseline.
// ---------------------------------------------------------------------------
template<int BM, int BN, int BK>
__global__ __launch_bounds__(256, 2)
void gemm_nt(const float* __restrict__ A, const float* __restrict__ B,
             float* __restrict__ C, int M, int N, int K)
{
    __shared__ float As[BK][BM + 4];
    __shared__ float Bs[BK][BN + 4];

    const int bm  = blockIdx.y * BM;
    const int bn  = blockIdx.x * BN;
    const int tid = threadIdx.x;            // 0..255
    const int tx  = tid % 16;                // N dir, 16 threads * 8 = 128
    const int ty  = tid / 16;                // M dir

    const int row4 = tid >> 2;               // 0..63
    const int col4 = (tid & 3) * 4;          // 0,4,8,12

    float acc[8][8];
    #pragma unroll
    for (int i = 0; i < 8; i++)
        #pragma unroll
        for (int j = 0; j < 8; j++)
            acc[i][j] = 0.0f;

    for (int k0 = 0; k0 < K; k0 += BK) {
        // load A tile [BM x BK] and B tile [BN x BK], transpose into smem
        #pragma unroll
        for (int r = 0; r < BM / 64; r++) {
            float4 av = *(const float4*)(A + (size_t)(bm + row4 + r * 64) * K + k0 + col4);
            As[col4 + 0][row4 + r * 64] = av.x;
            As[col4 + 1][row4 + r * 64] = av.y;
            As[col4 + 2][row4 + r * 64] = av.z;
            As[col4 + 3][row4 + r * 64] = av.w;
        }
        #pragma unroll
        for (int r = 0; r < BN / 64; r++) {
            float4 bv = *(const float4*)(B + (size_t)(bn + row4 + r * 64) * K + k0 + col4);
            Bs[col4 + 0][row4 + r * 64] = bv.x;
            Bs[col4 + 1][row4 + r * 64] = bv.y;
            Bs[col4 + 2][row4 + r * 64] = bv.z;
            Bs[col4 + 3][row4 + r * 64] = bv.w;
        }
        __syncthreads();

        #pragma unroll
        for (int kk = 0; kk < BK; kk++) {
            float ar[8], br[8];
            *(float4*)(ar)     = *(const float4*)&As[kk][ty * 8];
            *(float4*)(ar + 4) = *(const float4*)&As[kk][ty * 8 + 4];
            *(float4*)(br)     = *(const float4*)&Bs[kk][tx * 8];
            *(float4*)(br + 4) = *(const float4*)&Bs[kk][tx * 8 + 4];
            #pragma unroll
            for (int i = 0; i < 8; i++)
                #pragma unroll
                for (int j = 0; j < 8; j++)
                    acc[i][j] = fmaf(ar[i], br[j], acc[i][j]);
        }
        __syncthreads();
    }

    #pragma unroll
    for (int i = 0; i < 8; i++) {
        float* crow = C + (size_t)(bm + ty * 8 + i) * N + bn + tx * 8;
        float4 v0 = make_float4(acc[i][0], acc[i][1], acc[i][2], acc[i][3]);
        float4 v1 = make_float4(acc[i][4], acc[i][5], acc[i][6], acc[i][7]);
        *(float4*)(crow)     = v0;
        *(float4*)(crow + 4) = v1;
    }
}

// ---------------------------------------------------------------------------
// Bi-directional WKV scan, parallelized over time via associative segment
// scan. Block = 1024 threads = 32 channel-lanes x 32 time-chunk-warps.
// grid = (C/32, B, 2 directions). Fuses sigmoid(r) * y and writes out_cat.
// ---------------------------------------------------------------------------
__global__ __launch_bounds__(1024)
void wkv_scan(const float* __restrict__ rkv,
              const float* __restrict__ td,  const float* __restrict__ tf,
              const float* __restrict__ tdr, const float* __restrict__ tfr,
              float* __restrict__ cat)
{
    __shared__ float sA[32 * 33];
    __shared__ float sM[32 * 33];
    __shared__ float sN[32 * 33];
    __shared__ float sD[32 * 33];

    const int cx  = threadIdx.x & 31;   // channel lane
    const int j   = threadIdx.x >> 5;   // time-chunk (warp id)
    const int c   = blockIdx.x * 32 + cx;
    const int b   = blockIdx.y;
    const int dir = blockIdx.z;

    const float w = -__expf(dir ? tdr[c] : td[c]);
    const float u =          dir ? tfr[c] : tf[c];

    const int koff = (dir ? 4 * CDIM : 1 * CDIM) + c;
    const int voff = koff + CDIM;
    const int roff = (dir ? 3 * CDIM : 0) + c;

    const float* base = rkv + (size_t)(b * TDIM) * D6;

    const int tbase = dir ? (TDIM - 1 - j * CHUNK) : (j * CHUNK);
    const int tstep = dir ? -1 : 1;

    // ---- Pass 1: per-chunk segment summary (zero-init recurrence) ----
    float num = 0.f, den = 0.f, mx = -1e38f;
    #pragma unroll 4
    for (int i = 0; i < CHUNK; i++) {
        const size_t row = (size_t)(tbase + tstep * i) * D6;
        const float k = base[row + koff];
        const float v = base[row + voff];
        const float mw = mx + w;
        const float mn = fmaxf(mw, k);
        const float e1 = __expf(mw - mn);
        const float e2 = __expf(k  - mn);
        num = e1 * num + e2 * v;
        den = e1 * den + e2;
        mx  = mn;
    }

    // summary: state_out = e^{a} * state_in + e^{m} * (pn, pd)
    sA[j * 33 + cx] = (float)CHUNK * w;
    sM[j * 33 + cx] = mx;
    sN[j * 33 + cx] = num;
    sD[j * 33 + cx] = den;
    __syncthreads();

    // ---- Warp-shuffle exclusive scan. Warp `j` now scans channel index `j`;
    //      lane `cx` holds chunk `cx`'s summary (transposed via smem). ----
    {
        const int cl = cx;   // chunk index (lane)
        const int ch = j;    // channel index (warp)
        float a  = sA[cl * 33 + ch];
        float m  = sM[cl * 33 + ch];
        float pn = sN[cl * 33 + ch];
        float pd = sD[cl * 33 + ch];

        #pragma unroll
        for (int off = 1; off < 32; off <<= 1) {
            const float a2  = __shfl_up_sync(0xFFFFFFFFu, a,  off);
            const float m2  = __shfl_up_sync(0xFFFFFFFFu, m,  off);
            const float pn2 = __shfl_up_sync(0xFFFFFFFFu, pn, off);
            const float pd2 = __shfl_up_sync(0xFFFFFFFFu, pd, off);
            if (cl >= off) {
                // combine(prev=(a2,m2,pn2,pd2), cur=(a,m,pn,pd))
                const float mm = fmaxf(m2 + a, m);
                const float s1 = __expf(m2 + a - mm);
                const float s2 = __expf(m     - mm);
                pn = s1 * pn2 + s2 * pn;
                pd = s1 * pd2 + s2 * pd;
                m  = mm;
                a  = a + a2;
            }
        }
        // exclusive prefix
        float pm  = __shfl_up_sync(0xFFFFFFFFu, m,  1);
        float ppn = __shfl_up_sync(0xFFFFFFFFu, pn, 1);
        float ppd = __shfl_up_sync(0xFFFFFFFFu, pd, 1);
        if (cl == 0) { pm = -1e38f; ppn = 0.f; ppd = 0.f; }
        sM[cl * 33 + ch] = pm;
        sN[cl * 33 + ch] = ppn;
        sD[cl * 33 + ch] = ppd;
    }
    __syncthreads();

    // ---- Pass 2: replay chunk with correct prefix, emit sigmoid(r)*y ----
    mx  = sM[j * 33 + cx];
    num = sN[j * 33 + cx];
    den = sD[j * 33 + cx];

    const int dcol = dir * CDIM + c;
    #pragma unroll 2
    for (int i = 0; i < CHUNK; i++) {
        const int t = tbase + tstep * i;
        const size_t row = (size_t)t * D6;
        const float k = base[row + koff];
        const float v = base[row + voff];
        const float r = base[row + roff];

        const float ku = k + u;
        const float m1 = fmaxf(mx, ku);
        const float e1 = __expf(mx - m1);
        const float e2 = __expf(ku - m1);
        const float y  = (e1 * num + e2 * v) / (e1 * den + e2);
        const float sg = 1.f / (1.f + __expf(-r));

        cat[(size_t)(b * TDIM + t) * D2 + dcol] = y * sg;

        const float mw  = mx + w;
        const float mn  = fmaxf(mw, k);
        const float e1s = __expf(mw - mn);
        const float e2s = __expf(k  - mn);
        num = e1s * num + e2s * v;
        den = e1s * den + e2s;
        mx  = mn;
    }
}

// ---------------------------------------------------------------------------
extern "C" void kernel_launch(void* const* d_in, const int* in_sizes, int n_in,
                              void* d_out, int out_size)
{
    const float* x     = (const float*)d_in[0];   // [B,T,C]
    const float* rkv_w = (const float*)d_in[1];   // [6C, C]
    const float* out_w = (const float*)d_in[2];   // [C, 2C]
    const float* td    = (const float*)d_in[3];   // [C]
    const float* tf    = (const float*)d_in[4];   // [C]
    const float* tdr   = (const float*)d_in[5];   // [C]
    const float* tfr   = (const float*)d_in[6];   // [C]
    float* out = (float*)d_out;                   // [B,T,C]

    float* rkv = nullptr;
    float* cat = nullptr;
    cudaGetSymbolAddress((void**)&rkv, g_rkv);
    cudaGetSymbolAddress((void**)&cat, g_cat);

    // GEMM1: rkv[8192,6144] = x[8192,1024] @ rkv_w[6144,1024]^T
    {
        dim3 grid(D6 / 128, MROWS / 128);
        gemm_nt<128, 128, 16><<<grid, 256>>>(x, rkv_w, rkv, MROWS, D6, CDIM);
    }

    // Bi-directional WKV scan + gating, writes out_cat[8192, 2048]
    {
        dim3 grid(CDIM / 32, BDIM, 2);
        wkv_scan<<<grid, 1024>>>(rkv, td, tf, tdr, tfr, cat);
    }

    // GEMM2: out[8192,1024] = cat[8192,2048] @ out_w[1024,2048]^T
    {
        dim3 grid(CDIM / 128, MROWS / 128);
        gemm_nt<128, 128, 16><<<grid, 256>>>(cat, out_w, out, MROWS, CDIM, D2);
    }
}

// round 4
// speedup vs baseline: 2.1277x; 2.1277x over previous
#include <cuda_runtime.h>
#include <cstdint>

#define BDIM 4
#define TDIM 2048
#define CDIM 1024
#define D6   (6 * CDIM)          // 6144
#define D2   (2 * CDIM)          // 2048
#define MROWS (BDIM * TDIM)      // 8192
#define CHUNK 64                 // T / 32 warps (scan)

// Scratch (allocation-free rule: __device__ globals)
__device__ float g_rkv[(size_t)MROWS * D6];   // [B*T, 6C]
__device__ float g_cat[(size_t)MROWS * D2];   // [B*T, 2C]

// ============================================================================
// TF32 mma.sync GEMM (NT): C[M,N] = A[M,K] * B[N,K]^T, fp32 in/out.
// BM=128, BN=128, BK=32; 256 thr = 8 warps (2M x 4N), warp tile 64x32,
// mma.m16n8k8.tf32, cp.async double-buffered smem (pitch 36 -> no LDS
// bank conflicts on fragment loads).
// ============================================================================
#define BM 128
#define BN 128
#define BK 32
#define PITCH 36                              // floats per smem row
#define A_FLOATS (BM * PITCH)                 // 4608
#define B_FLOATS (BN * PITCH)                 // 4608
#define STAGE_FLOATS (A_FLOATS + B_FLOATS)    // 9216
#define GT_SMEM_BYTES (2 * STAGE_FLOATS * 4)  // 73728

__device__ __forceinline__ uint32_t smem_u32(const void* p) {
    uint32_t a;
    asm("{ .reg .u64 t; cvta.to.shared.u64 t, %1; cvt.u32.u64 %0, t; }"
        : "=r"(a) : "l"(p));
    return a;
}

__device__ __forceinline__ void cp_async16(uint32_t dst, const float* src) {
    asm volatile("cp.async.cg.shared.global [%0], [%1], 16;"
                 :: "r"(dst), "l"(src) : "memory");
}
__device__ __forceinline__ void cp_commit() {
    asm volatile("cp.async.commit_group;" ::: "memory");
}
__device__ __forceinline__ void cp_wait0() {
    asm volatile("cp.async.wait_group 0;" ::: "memory");
}

__device__ __forceinline__ uint32_t to_tf32(float f) {
    uint32_t r;
    asm("cvt.rna.tf32.f32 %0, %1;" : "=r"(r) : "f"(f));
    return r;
}

__device__ __forceinline__ void mma_tf32(
    float& c0, float& c1, float& c2, float& c3,
    uint32_t a0, uint32_t a1, uint32_t a2, uint32_t a3,
    uint32_t b0, uint32_t b1)
{
    asm volatile(
        "mma.sync.aligned.m16n8k8.row.col.f32.tf32.tf32.f32 "
        "{%0,%1,%2,%3}, {%4,%5,%6,%7}, {%8,%9}, {%0,%1,%2,%3};"
        : "+f"(c0), "+f"(c1), "+f"(c2), "+f"(c3)
        : "r"(a0), "r"(a1), "r"(a2), "r"(a3), "r"(b0), "r"(b1));
}

__global__ __launch_bounds__(256, 2)
void gemm_mma(const float* __restrict__ A, const float* __restrict__ B,
              float* __restrict__ C, int M, int N, int K)
{
    extern __shared__ float sm[];
    float* sA[2] = { sm,                 sm + STAGE_FLOATS };
    float* sB[2] = { sm + A_FLOATS,      sm + STAGE_FLOATS + A_FLOATS };

    const int tid  = threadIdx.x;
    const int wid  = tid >> 5;
    const int lane = tid & 31;
    const int bm   = blockIdx.y * BM;
    const int bn   = blockIdx.x * BN;

    const int warpM = (wid >> 2) * 64;    // 0 or 64
    const int warpN = (wid & 3) * 32;     // 0..96

    // loader indices: 1024 float4 per tile, 4 per thread
    const int lrow = tid >> 1;                  // 0..127 (2 thr/row, 2 f4 each)
    const int lc0  = (tid & 1) * 2;             // float4 slot 0/2 then +1

    const uint32_t sAu = smem_u32(sm);

    float acc[4][4][4];
    #pragma unroll
    for (int i = 0; i < 4; i++)
        #pragma unroll
        for (int j = 0; j < 4; j++)
            #pragma unroll
            for (int q = 0; q < 4; q++) acc[i][j][q] = 0.f;

    const int KT = K / BK;

    // prologue: load stage 0
    {
        const float* Ab = A + (size_t)(bm + lrow) * K;
        const float* Bb = B + (size_t)(bn + lrow) * K;
        uint32_t sa = sAu + (lrow * PITCH) * 4;
        uint32_t sb = sAu + (A_FLOATS + lrow * PITCH) * 4;
        #pragma unroll
        for (int q = 0; q < 2; q++) {
            const int c4 = lc0 + q;             // 0..3  (cols 0..15)
            cp_async16(sa + (c4 * 4) * 4,        Ab + c4 * 4);
            cp_async16(sa + ((c4 + 4) * 4) * 4,  Ab + (c4 + 4) * 4);
            cp_async16(sb + (c4 * 4) * 4,        Bb + c4 * 4);
            cp_async16(sb + ((c4 + 4) * 4) * 4,  Bb + (c4 + 4) * 4);
        }
        cp_commit();
    }

    for (int it = 0; it < KT; it++) {
        cp_wait0();
        __syncthreads();

        const int cur = it & 1;
        if (it + 1 < KT) {
            const int nxt = cur ^ 1;
            const int k0  = (it + 1) * BK;
            const float* Ab = A + (size_t)(bm + lrow) * K + k0;
            const float* Bb = B + (size_t)(bn + lrow) * K + k0;
            uint32_t sa = sAu + (nxt * STAGE_FLOATS + lrow * PITCH) * 4;
            uint32_t sb = sAu + (nxt * STAGE_FLOATS + A_FLOATS + lrow * PITCH) * 4;
            #pragma unroll
            for (int q = 0; q < 2; q++) {
                const int c4 = lc0 + q;
                cp_async16(sa + (c4 * 4) * 4,        Ab + c4 * 4);
                cp_async16(sa + ((c4 + 4) * 4) * 4,  Ab + (c4 + 4) * 4);
                cp_async16(sb + (c4 * 4) * 4,        Bb + c4 * 4);
                cp_async16(sb + ((c4 + 4) * 4) * 4,  Bb + (c4 + 4) * 4);
            }
            cp_commit();
        }

        const float* cA = sA[cur];
        const float* cB = sB[cur];
        const int r4 = lane >> 2;      // 0..7
        const int q4 = lane & 3;       // 0..3

        #pragma unroll
        for (int ks = 0; ks < 4; ks++) {
            const int kb = ks * 8;
            uint32_t af[4][4];
            #pragma unroll
            for (int mi = 0; mi < 4; mi++) {
                const int r0 = warpM + mi * 16 + r4;
                af[mi][0] = to_tf32(cA[r0 * PITCH + kb + q4]);
                af[mi][1] = to_tf32(cA[(r0 + 8) * PITCH + kb + q4]);
                af[mi][2] = to_tf32(cA[r0 * PITCH + kb + q4 + 4]);
                af[mi][3] = to_tf32(cA[(r0 + 8) * PITCH + kb + q4 + 4]);
            }
            uint32_t bf[4][2];
            #pragma unroll
            for (int ni = 0; ni < 4; ni++) {
                const int n0 = warpN + ni * 8 + r4;
                bf[ni][0] = to_tf32(cB[n0 * PITCH + kb + q4]);
                bf[ni][1] = to_tf32(cB[n0 * PITCH + kb + q4 + 4]);
            }
            #pragma unroll
            for (int mi = 0; mi < 4; mi++)
                #pragma unroll
                for (int ni = 0; ni < 4; ni++)
                    mma_tf32(acc[mi][ni][0], acc[mi][ni][1],
                             acc[mi][ni][2], acc[mi][ni][3],
                             af[mi][0], af[mi][1], af[mi][2], af[mi][3],
                             bf[ni][0], bf[ni][1]);
        }
        __syncthreads();
    }

    // epilogue: c0,c1 -> (row, 2q..2q+1); c2,c3 -> (row+8, ...)
    const int r4 = lane >> 2;
    const int q4 = lane & 3;
    #pragma unroll
    for (int mi = 0; mi < 4; mi++) {
        #pragma unroll
        for (int ni = 0; ni < 4; ni++) {
            const int row = bm + warpM + mi * 16 + r4;
            const int col = bn + warpN + ni * 8 + q4 * 2;
            float2 v0 = make_float2(acc[mi][ni][0], acc[mi][ni][1]);
            float2 v1 = make_float2(acc[mi][ni][2], acc[mi][ni][3]);
            *(float2*)(C + (size_t)row * N + col)       = v0;
            *(float2*)(C + (size_t)(row + 8) * N + col) = v1;
        }
    }
}

// ============================================================================
// Bi-directional WKV scan (verified correct in R1/R2).
// ============================================================================
__global__ __launch_bounds__(1024)
void wkv_scan(const float* __restrict__ rkv,
              const float* __restrict__ td,  const float* __restrict__ tf,
              const float* __restrict__ tdr, const float* __restrict__ tfr,
              float* __restrict__ cat)
{
    __shared__ float sA[32 * 33];
    __shared__ float sM[32 * 33];
    __shared__ float sN[32 * 33];
    __shared__ float sD[32 * 33];

    const int cx  = threadIdx.x & 31;
    const int j   = threadIdx.x >> 5;
    const int c   = blockIdx.x * 32 + cx;
    const int b   = blockIdx.y;
    const int dir = blockIdx.z;

    const float w = -__expf(dir ? tdr[c] : td[c]);
    const float u =          dir ? tfr[c] : tf[c];

    const int koff = (dir ? 4 * CDIM : 1 * CDIM) + c;
    const int voff = koff + CDIM;
    const int roff = (dir ? 3 * CDIM : 0) + c;

    const float* base = rkv + (size_t)(b * TDIM) * D6;

    const int tbase = dir ? (TDIM - 1 - j * CHUNK) : (j * CHUNK);
    const int tstep = dir ? -1 : 1;

    float num = 0.f, den = 0.f, mx = -1e38f;
    #pragma unroll 4
    for (int i = 0; i < CHUNK; i++) {
        const size_t row = (size_t)(tbase + tstep * i) * D6;
        const float k = base[row + koff];
        const float v = base[row + voff];
        const float mw = mx + w;
        const float mn = fmaxf(mw, k);
        const float e1 = __expf(mw - mn);
        const float e2 = __expf(k  - mn);
        num = e1 * num + e2 * v;
        den = e1 * den + e2;
        mx  = mn;
    }

    sA[j * 33 + cx] = (float)CHUNK * w;
    sM[j * 33 + cx] = mx;
    sN[j * 33 + cx] = num;
    sD[j * 33 + cx] = den;
    __syncthreads();

    {
        const int cl = cx;
        const int ch = j;
        float a  = sA[cl * 33 + ch];
        float m  = sM[cl * 33 + ch];
        float pn = sN[cl * 33 + ch];
        float pd = sD[cl * 33 + ch];

        #pragma unroll
        for (int off = 1; off < 32; off <<= 1) {
            const float a2  = __shfl_up_sync(0xFFFFFFFFu, a,  off);
            const float m2  = __shfl_up_sync(0xFFFFFFFFu, m,  off);
            const float pn2 = __shfl_up_sync(0xFFFFFFFFu, pn, off);
            const float pd2 = __shfl_up_sync(0xFFFFFFFFu, pd, off);
            if (cl >= off) {
                const float mm = fmaxf(m2 + a, m);
                const float s1 = __expf(m2 + a - mm);
                const float s2 = __expf(m     - mm);
                pn = s1 * pn2 + s2 * pn;
                pd = s1 * pd2 + s2 * pd;
                m  = mm;
                a  = a + a2;
            }
        }
        float pm  = __shfl_up_sync(0xFFFFFFFFu, m,  1);
        float ppn = __shfl_up_sync(0xFFFFFFFFu, pn, 1);
        float ppd = __shfl_up_sync(0xFFFFFFFFu, pd, 1);
        if (cl == 0) { pm = -1e38f; ppn = 0.f; ppd = 0.f; }
        sM[cl * 33 + ch] = pm;
        sN[cl * 33 + ch] = ppn;
        sD[cl * 33 + ch] = ppd;
    }
    __syncthreads();

    mx  = sM[j * 33 + cx];
    num = sN[j * 33 + cx];
    den = sD[j * 33 + cx];

    const int dcol = dir * CDIM + c;
    #pragma unroll 2
    for (int i = 0; i < CHUNK; i++) {
        const int t = tbase + tstep * i;
        const size_t row = (size_t)t * D6;
        const float k = base[row + koff];
        const float v = base[row + voff];
        const float r = base[row + roff];

        const float ku = k + u;
        const float m1 = fmaxf(mx, ku);
        const float e1 = __expf(mx - m1);
        const float e2 = __expf(ku - m1);
        const float y  = (e1 * num + e2 * v) / (e1 * den + e2);
        const float sg = 1.f / (1.f + __expf(-r));

        cat[(size_t)(b * TDIM + t) * D2 + dcol] = y * sg;

        const float mw  = mx + w;
        const float mn  = fmaxf(mw, k);
        const float e1s = __expf(mw - mn);
        const float e2s = __expf(k  - mn);
        num = e1s * num + e2s * v;
        den = e1s * den + e2s;
        mx  = mn;
    }
}

// ============================================================================
extern "C" void kernel_launch(void* const* d_in, const int* in_sizes, int n_in,
                              void* d_out, int out_size)
{
    const float* x     = (const float*)d_in[0];   // [B,T,C]
    const float* rkv_w = (const float*)d_in[1];   // [6C, C]
    const float* out_w = (const float*)d_in[2];   // [C, 2C]
    const float* td    = (const float*)d_in[3];
    const float* tf    = (const float*)d_in[4];
    const float* tdr   = (const float*)d_in[5];
    const float* tfr   = (const float*)d_in[6];
    float* out = (float*)d_out;                   // [B,T,C]

    float* rkv = nullptr;
    float* cat = nullptr;
    cudaGetSymbolAddress((void**)&rkv, g_rkv);
    cudaGetSymbolAddress((void**)&cat, g_cat);

    cudaFuncSetAttribute(gemm_mma, cudaFuncAttributeMaxDynamicSharedMemorySize,
                         GT_SMEM_BYTES);

    // GEMM1: rkv[8192,6144] = x[8192,1024] @ rkv_w[6144,1024]^T
    {
        dim3 grid(D6 / BN, MROWS / BM);   // (48, 64)
        gemm_mma<<<grid, 256, GT_SMEM_BYTES>>>(x, rkv_w, rkv, MROWS, D6, CDIM);
    }

    // Bi-directional WKV scan + gating -> cat[8192, 2048]
    {
        dim3 grid(CDIM / 32, BDIM, 2);
        wkv_scan<<<grid, 1024>>>(rkv, td, tf, tdr, tfr, cat);
    }

    // GEMM2: out[8192,1024] = cat[8192,2048] @ out_w[1024,2048]^T
    {
        dim3 grid(CDIM / BN, MROWS / BM); // (8, 64)
        gemm_mma<<<grid, 256, GT_SMEM_BYTES>>>(cat, out_w, out, MROWS, CDIM, D2);
    }
}

// round 5
// speedup vs baseline: 2.5742x; 1.2099x over previous
#include <cuda_runtime.h>
#include <cstdint>

#define BDIM 4
#define TDIM 2048
#define CDIM 1024
#define D6   (6 * CDIM)          // 6144
#define D2   (2 * CDIM)          // 2048
#define MROWS (BDIM * TDIM)      // 8192
#define CHUNK 64                 // T / 32 warps (scan)

// Scratch (allocation-free rule: __device__ globals)
__device__ float g_rkv[(size_t)MROWS * D6];   // [B*T, 6C]
__device__ float g_cat[(size_t)MROWS * D2];   // [B*T, 2C] (tf32-rounded)
__device__ float g_xc [(size_t)MROWS * CDIM]; // x rounded to tf32
__device__ float g_w1 [(size_t)D6 * CDIM];    // rkv_w rounded
__device__ float g_w2 [(size_t)CDIM * D2];    // out_w rounded

__device__ __forceinline__ uint32_t smem_u32(const void* p) {
    uint32_t a;
    asm("{ .reg .u64 t; cvta.to.shared.u64 t, %1; cvt.u32.u64 %0, t; }"
        : "=r"(a) : "l"(p));
    return a;
}
__device__ __forceinline__ void cp_async16(uint32_t dst, const float* src) {
    asm volatile("cp.async.cg.shared.global [%0], [%1], 16;"
                 :: "r"(dst), "l"(src) : "memory");
}
__device__ __forceinline__ void cp_commit() {
    asm volatile("cp.async.commit_group;" ::: "memory");
}
__device__ __forceinline__ void cp_wait0() {
    asm volatile("cp.async.wait_group 0;" ::: "memory");
}
__device__ __forceinline__ uint32_t to_tf32(float f) {
    uint32_t r;
    asm("cvt.rna.tf32.f32 %0, %1;" : "=r"(r) : "f"(f));
    return r;
}
__device__ __forceinline__ void mma_tf32(
    float& c0, float& c1, float& c2, float& c3,
    uint32_t a0, uint32_t a1, uint32_t a2, uint32_t a3,
    uint32_t b0, uint32_t b1)
{
    asm volatile(
        "mma.sync.aligned.m16n8k8.row.col.f32.tf32.tf32.f32 "
        "{%0,%1,%2,%3}, {%4,%5,%6,%7}, {%8,%9}, {%0,%1,%2,%3};"
        : "+f"(c0), "+f"(c1), "+f"(c2), "+f"(c3)
        : "r"(a0), "r"(a1), "r"(a2), "r"(a3), "r"(b0), "r"(b1));
}
__device__ __forceinline__ void ldsm_x4(uint32_t* r, uint32_t addr) {
    asm volatile("ldmatrix.sync.aligned.m8n8.x4.shared.b16 {%0,%1,%2,%3}, [%4];"
                 : "=r"(r[0]), "=r"(r[1]), "=r"(r[2]), "=r"(r[3]) : "r"(addr));
}
__device__ __forceinline__ void ldsm_x2(uint32_t* r, uint32_t addr) {
    asm volatile("ldmatrix.sync.aligned.m8n8.x2.shared.b16 {%0,%1}, [%2];"
                 : "=r"(r[0]), "=r"(r[1]) : "r"(addr));
}

// ============================================================================
// Pre-pass: round fp32 -> tf32 (RNA) in gmem. n multiple of 4.
// ============================================================================
__global__ void round_tf32_kernel(const float* __restrict__ in,
                                  float* __restrict__ out, int n4)
{
    int i = blockIdx.x * blockDim.x + threadIdx.x;
    if (i < n4) {
        float4 v = ((const float4*)in)[i];
        v.x = __uint_as_float(to_tf32(v.x));
        v.y = __uint_as_float(to_tf32(v.y));
        v.z = __uint_as_float(to_tf32(v.z));
        v.w = __uint_as_float(to_tf32(v.w));
        ((float4*)out)[i] = v;
    }
}

// ============================================================================
// TF32 mma.sync GEMM (NT): C[M,N] = A[M,K] * B[N,K]^T.
// Inputs MUST be pre-rounded to tf32. ldmatrix fragment loads.
// BM=128, BN=128, BK=32; 256 thr = 8 warps (2M x 4N), warp tile 64x32.
// ============================================================================
#define BM 128
#define BN 128
#define BK 32
#define PITCH 36                              // floats per smem row
#define A_FLOATS (BM * PITCH)                 // 4608
#define B_FLOATS (BN * PITCH)                 // 4608
#define STAGE_FLOATS (A_FLOATS + B_FLOATS)    // 9216
#define GT_SMEM_BYTES (2 * STAGE_FLOATS * 4)  // 73728

__global__ __launch_bounds__(256, 2)
void gemm_mma(const float* __restrict__ A, const float* __restrict__ B,
              float* __restrict__ C, int M, int N, int K)
{
    extern __shared__ float sm[];

    const int tid  = threadIdx.x;
    const int wid  = tid >> 5;
    const int lane = tid & 31;
    const int bm   = blockIdx.y * BM;
    const int bn   = blockIdx.x * BN;

    const int warpM = (wid >> 2) * 64;    // 0 or 64
    const int warpN = (wid & 3) * 32;     // 0..96

    // loader indices: 1024 float4 per tile half, 2 rows per 2 threads
    const int lrow = tid >> 1;
    const int lc0  = (tid & 1) * 2;

    const uint32_t sAu = smem_u32(sm);

    // ldmatrix lane base offsets (bytes within stage)
    const int l8  = lane & 7;
    const int lhi = (lane >> 3) & 1;
    const int lq  = (lane >> 4) & 1;
    const uint32_t laneA = (uint32_t)((warpM + l8 + lhi * 8) * PITCH) * 4u + lq * 16u;
    const uint32_t laneB = (uint32_t)((A_FLOATS + (warpN + l8) * PITCH)) * 4u + lhi * 16u;

    float acc[4][4][4];
    #pragma unroll
    for (int i = 0; i < 4; i++)
        #pragma unroll
        for (int j = 0; j < 4; j++)
            #pragma unroll
            for (int q = 0; q < 4; q++) acc[i][j][q] = 0.f;

    const int KT = K / BK;

    // prologue: stage 0
    {
        const float* Ab = A + (size_t)(bm + lrow) * K;
        const float* Bb = B + (size_t)(bn + lrow) * K;
        uint32_t sa = sAu + (lrow * PITCH) * 4;
        uint32_t sb = sAu + (A_FLOATS + lrow * PITCH) * 4;
        #pragma unroll
        for (int q = 0; q < 2; q++) {
            const int c4 = lc0 + q;
            cp_async16(sa + (c4 * 4) * 4,        Ab + c4 * 4);
            cp_async16(sa + ((c4 + 4) * 4) * 4,  Ab + (c4 + 4) * 4);
            cp_async16(sb + (c4 * 4) * 4,        Bb + c4 * 4);
            cp_async16(sb + ((c4 + 4) * 4) * 4,  Bb + (c4 + 4) * 4);
        }
        cp_commit();
    }

    for (int it = 0; it < KT; it++) {
        cp_wait0();
        __syncthreads();

        const int cur = it & 1;
        if (it + 1 < KT) {
            const int nxt = cur ^ 1;
            const int k0  = (it + 1) * BK;
            const float* Ab = A + (size_t)(bm + lrow) * K + k0;
            const float* Bb = B + (size_t)(bn + lrow) * K + k0;
            uint32_t sa = sAu + (nxt * STAGE_FLOATS + lrow * PITCH) * 4;
            uint32_t sb = sAu + (nxt * STAGE_FLOATS + A_FLOATS + lrow * PITCH) * 4;
            #pragma unroll
            for (int q = 0; q < 2; q++) {
                const int c4 = lc0 + q;
                cp_async16(sa + (c4 * 4) * 4,        Ab + c4 * 4);
                cp_async16(sa + ((c4 + 4) * 4) * 4,  Ab + (c4 + 4) * 4);
                cp_async16(sb + (c4 * 4) * 4,        Bb + c4 * 4);
                cp_async16(sb + ((c4 + 4) * 4) * 4,  Bb + (c4 + 4) * 4);
            }
            cp_commit();
        }

        const uint32_t stg = sAu + cur * (STAGE_FLOATS * 4);

        #pragma unroll
        for (int ks = 0; ks < 4; ks++) {
            uint32_t af[4][4];
            #pragma unroll
            for (int mi = 0; mi < 4; mi++)
                ldsm_x4(af[mi], stg + laneA + mi * (16 * PITCH * 4) + ks * 32);
            uint32_t bf[4][2];
            #pragma unroll
            for (int ni = 0; ni < 4; ni++)
                ldsm_x2(bf[ni], stg + laneB + ni * (8 * PITCH * 4) + ks * 32);
            #pragma unroll
            for (int mi = 0; mi < 4; mi++)
                #pragma unroll
                for (int ni = 0; ni < 4; ni++)
                    mma_tf32(acc[mi][ni][0], acc[mi][ni][1],
                             acc[mi][ni][2], acc[mi][ni][3],
                             af[mi][0], af[mi][1], af[mi][2], af[mi][3],
                             bf[ni][0], bf[ni][1]);
        }
        __syncthreads();
    }

    const int r4 = lane >> 2;
    const int q4 = lane & 3;
    #pragma unroll
    for (int mi = 0; mi < 4; mi++) {
        #pragma unroll
        for (int ni = 0; ni < 4; ni++) {
            const int row = bm + warpM + mi * 16 + r4;
            const int col = bn + warpN + ni * 8 + q4 * 2;
            float2 v0 = make_float2(acc[mi][ni][0], acc[mi][ni][1]);
            float2 v1 = make_float2(acc[mi][ni][2], acc[mi][ni][3]);
            *(float2*)(C + (size_t)row * N + col)       = v0;
            *(float2*)(C + (size_t)(row + 8) * N + col) = v1;
        }
    }
}

// ============================================================================
// Bi-directional WKV scan. Emits cat pre-rounded to tf32 for GEMM2.
// ============================================================================
__global__ __launch_bounds__(1024)
void wkv_scan(const float* __restrict__ rkv,
              const float* __restrict__ td,  const float* __restrict__ tf,
              const float* __restrict__ tdr, const float* __restrict__ tfr,
              float* __restrict__ cat)
{
    __shared__ float sA[32 * 33];
    __shared__ float sM[32 * 33];
    __shared__ float sN[32 * 33];
    __shared__ float sD[32 * 33];

    const int cx  = threadIdx.x & 31;
    const int j   = threadIdx.x >> 5;
    const int c   = blockIdx.x * 32 + cx;
    const int b   = blockIdx.y;
    const int dir = blockIdx.z;

    const float w = -__expf(dir ? tdr[c] : td[c]);
    const float u =          dir ? tfr[c] : tf[c];

    const int koff = (dir ? 4 * CDIM : 1 * CDIM) + c;
    const int voff = koff + CDIM;
    const int roff = (dir ? 3 * CDIM : 0) + c;

    const float* base = rkv + (size_t)(b * TDIM) * D6;

    const int tbase = dir ? (TDIM - 1 - j * CHUNK) : (j * CHUNK);
    const int tstep = dir ? -1 : 1;

    float num = 0.f, den = 0.f, mx = -1e38f;
    #pragma unroll 4
    for (int i = 0; i < CHUNK; i++) {
        const size_t row = (size_t)(tbase + tstep * i) * D6;
        const float k = base[row + koff];
        const float v = base[row + voff];
        const float mw = mx + w;
        const float mn = fmaxf(mw, k);
        const float e1 = __expf(mw - mn);
        const float e2 = __expf(k  - mn);
        num = e1 * num + e2 * v;
        den = e1 * den + e2;
        mx  = mn;
    }

    sA[j * 33 + cx] = (float)CHUNK * w;
    sM[j * 33 + cx] = mx;
    sN[j * 33 + cx] = num;
    sD[j * 33 + cx] = den;
    __syncthreads();

    {
        const int cl = cx;
        const int ch = j;
        float a  = sA[cl * 33 + ch];
        float m  = sM[cl * 33 + ch];
        float pn = sN[cl * 33 + ch];
        float pd = sD[cl * 33 + ch];

        #pragma unroll
        for (int off = 1; off < 32; off <<= 1) {
            const float a2  = __shfl_up_sync(0xFFFFFFFFu, a,  off);
            const float m2  = __shfl_up_sync(0xFFFFFFFFu, m,  off);
            const float pn2 = __shfl_up_sync(0xFFFFFFFFu, pn, off);
            const float pd2 = __shfl_up_sync(0xFFFFFFFFu, pd, off);
            if (cl >= off) {
                const float mm = fmaxf(m2 + a, m);
                const float s1 = __expf(m2 + a - mm);
                const float s2 = __expf(m     - mm);
                pn = s1 * pn2 + s2 * pn;
                pd = s1 * pd2 + s2 * pd;
                m  = mm;
                a  = a + a2;
            }
        }
        float pm  = __shfl_up_sync(0xFFFFFFFFu, m,  1);
        float ppn = __shfl_up_sync(0xFFFFFFFFu, pn, 1);
        float ppd = __shfl_up_sync(0xFFFFFFFFu, pd, 1);
        if (cl == 0) { pm = -1e38f; ppn = 0.f; ppd = 0.f; }
        sM[cl * 33 + ch] = pm;
        sN[cl * 33 + ch] = ppn;
        sD[cl * 33 + ch] = ppd;
    }
    __syncthreads();

    mx  = sM[j * 33 + cx];
    num = sN[j * 33 + cx];
    den = sD[j * 33 + cx];

    const int dcol = dir * CDIM + c;
    #pragma unroll 2
    for (int i = 0; i < CHUNK; i++) {
        const int t = tbase + tstep * i;
        const size_t row = (size_t)t * D6;
        const float k = base[row + koff];
        const float v = base[row + voff];
        const float r = base[row + roff];

        const float ku = k + u;
        const float m1 = fmaxf(mx, ku);
        const float e1 = __expf(mx - m1);
        const float e2 = __expf(ku - m1);
        const float y  = (e1 * num + e2 * v) / (e1 * den + e2);
        const float sg = 1.f / (1.f + __expf(-r));

        cat[(size_t)(b * TDIM + t) * D2 + dcol] =
            __uint_as_float(to_tf32(y * sg));

        const float mw  = mx + w;
        const float mn  = fmaxf(mw, k);
        const float e1s = __expf(mw - mn);
        const float e2s = __expf(k  - mn);
        num = e1s * num + e2s * v;
        den = e1s * den + e2s;
        mx  = mn;
    }
}

// ============================================================================
extern "C" void kernel_launch(void* const* d_in, const int* in_sizes, int n_in,
                              void* d_out, int out_size)
{
    const float* x     = (const float*)d_in[0];   // [B,T,C]
    const float* rkv_w = (const float*)d_in[1];   // [6C, C]
    const float* out_w = (const float*)d_in[2];   // [C, 2C]
    const float* td    = (const float*)d_in[3];
    const float* tf    = (const float*)d_in[4];
    const float* tdr   = (const float*)d_in[5];
    const float* tfr   = (const float*)d_in[6];
    float* out = (float*)d_out;                   // [B,T,C]

    float *rkv, *cat, *xc, *w1, *w2;
    cudaGetSymbolAddress((void**)&rkv, g_rkv);
    cudaGetSymbolAddress((void**)&cat, g_cat);
    cudaGetSymbolAddress((void**)&xc,  g_xc);
    cudaGetSymbolAddress((void**)&w1,  g_w1);
    cudaGetSymbolAddress((void**)&w2,  g_w2);

    cudaFuncSetAttribute(gemm_mma, cudaFuncAttributeMaxDynamicSharedMemorySize,
                         GT_SMEM_BYTES);

    // Pre-round inputs to tf32 (RNA)
    {
        const int nx = MROWS * CDIM / 4, n1 = D6 * CDIM / 4, n2 = CDIM * D2 / 4;
        round_tf32_kernel<<<(nx + 255) / 256, 256>>>(x,     xc, nx);
        round_tf32_kernel<<<(n1 + 255) / 256, 256>>>(rkv_w, w1, n1);
        round_tf32_kernel<<<(n2 + 255) / 256, 256>>>(out_w, w2, n2);
    }

    // GEMM1: rkv[8192,6144] = xc @ w1^T
    {
        dim3 grid(D6 / BN, MROWS / BM);   // (48, 64)
        gemm_mma<<<grid, 256, GT_SMEM_BYTES>>>(xc, w1, rkv, MROWS, D6, CDIM);
    }

    // Bi-directional WKV scan + gating -> cat[8192, 2048] (tf32-rounded)
    {
        dim3 grid(CDIM / 32, BDIM, 2);
        wkv_scan<<<grid, 1024>>>(rkv, td, tf, tdr, tfr, cat);
    }

    // GEMM2: out[8192,1024] = cat @ w2^T
    {
        dim3 grid(CDIM / BN, MROWS / BM); // (8, 64)
        gemm_mma<<<grid, 256, GT_SMEM_BYTES>>>(cat, w2, out, MROWS, CDIM, D2);
    }
}

// round 6
// speedup vs baseline: 2.7275x; 1.0595x over previous
#include <cuda_runtime.h>
#include <cstdint>

#define BDIM 4
#define TDIM 2048
#define CDIM 1024
#define D6   (6 * CDIM)          // 6144
#define D2   (2 * CDIM)          // 2048
#define MROWS (BDIM * TDIM)      // 8192
#define CHUNK 64                 // T / 32 warps (scan)

// Scratch (allocation-free rule: __device__ globals)
__device__ float g_rkv[(size_t)MROWS * D6];   // [B*T, 6C]
__device__ float g_cat[(size_t)MROWS * D2];   // [B*T, 2C] (tf32-rounded)
__device__ float g_xc [(size_t)MROWS * CDIM]; // x rounded to tf32
__device__ float g_w1 [(size_t)D6 * CDIM];    // rkv_w rounded
__device__ float g_w2 [(size_t)CDIM * D2];    // out_w rounded

__device__ __forceinline__ uint32_t smem_u32(const void* p) {
    uint32_t a;
    asm("{ .reg .u64 t; cvta.to.shared.u64 t, %1; cvt.u32.u64 %0, t; }"
        : "=r"(a) : "l"(p));
    return a;
}
__device__ __forceinline__ void cp_async16(uint32_t dst, const float* src) {
    asm volatile("cp.async.cg.shared.global [%0], [%1], 16;"
                 :: "r"(dst), "l"(src) : "memory");
}
__device__ __forceinline__ void cp_commit() {
    asm volatile("cp.async.commit_group;" ::: "memory");
}
__device__ __forceinline__ void cp_wait1() {
    asm volatile("cp.async.wait_group 1;" ::: "memory");
}
__device__ __forceinline__ void cp_wait0() {
    asm volatile("cp.async.wait_group 0;" ::: "memory");
}
__device__ __forceinline__ uint32_t to_tf32(float f) {
    uint32_t r;
    asm("cvt.rna.tf32.f32 %0, %1;" : "=r"(r) : "f"(f));
    return r;
}
__device__ __forceinline__ void mma_tf32(
    float& c0, float& c1, float& c2, float& c3,
    uint32_t a0, uint32_t a1, uint32_t a2, uint32_t a3,
    uint32_t b0, uint32_t b1)
{
    asm volatile(
        "mma.sync.aligned.m16n8k8.row.col.f32.tf32.tf32.f32 "
        "{%0,%1,%2,%3}, {%4,%5,%6,%7}, {%8,%9}, {%0,%1,%2,%3};"
        : "+f"(c0), "+f"(c1), "+f"(c2), "+f"(c3)
        : "r"(a0), "r"(a1), "r"(a2), "r"(a3), "r"(b0), "r"(b1));
}
__device__ __forceinline__ void ldsm_x4(uint32_t* r, uint32_t addr) {
    asm volatile("ldmatrix.sync.aligned.m8n8.x4.shared.b16 {%0,%1,%2,%3}, [%4];"
                 : "=r"(r[0]), "=r"(r[1]), "=r"(r[2]), "=r"(r[3]) : "r"(addr));
}

// ============================================================================
// Pre-pass: round fp32 -> tf32 (RNA) in gmem. n multiple of 4.
// ============================================================================
__global__ void round_tf32_kernel(const float* __restrict__ in,
                                  float* __restrict__ out, int n4)
{
    int i = blockIdx.x * blockDim.x + threadIdx.x;
    if (i < n4) {
        float4 v = ((const float4*)in)[i];
        v.x = __uint_as_float(to_tf32(v.x));
        v.y = __uint_as_float(to_tf32(v.y));
        v.z = __uint_as_float(to_tf32(v.z));
        v.w = __uint_as_float(to_tf32(v.w));
        ((float4*)out)[i] = v;
    }
}

// ============================================================================
// TF32 mma.sync GEMM (NT): C[M,N] = A[M,K] * B[N,K]^T.
// Inputs pre-rounded to tf32. ldmatrix fragment loads.
// BM=128, BN=128, BK=32; 256 thr = 8 warps (2M x 4N), warp tile 64x32.
// 3-stage cp.async ring (wait_group 1), ONE barrier per K-iter.
// ============================================================================
#define BM 128
#define BN 128
#define BK 32
#define NSTAGE 3
#define PITCH 36                              // floats per smem row
#define A_FLOATS (BM * PITCH)                 // 4608
#define B_FLOATS (BN * PITCH)                 // 4608
#define STAGE_FLOATS (A_FLOATS + B_FLOATS)    // 9216
#define GT_SMEM_BYTES (NSTAGE * STAGE_FLOATS * 4)  // 110592

__global__ __launch_bounds__(256, 2)
void gemm_mma(const float* __restrict__ A, const float* __restrict__ B,
              float* __restrict__ C, int M, int N, int K)
{
    extern __shared__ float sm[];

    const int tid  = threadIdx.x;
    const int wid  = tid >> 5;
    const int lane = tid & 31;
    const int bm   = blockIdx.y * BM;
    const int bn   = blockIdx.x * BN;

    const int warpM = (wid >> 2) * 64;    // 0 or 64
    const int warpN = (wid & 3) * 32;     // 0..96

    const int lrow = tid >> 1;            // loader row 0..127
    const int lc0  = (tid & 1) * 2;       // loader float4 col base

    const uint32_t sAu = smem_u32(sm);

    // ldmatrix lane addressing
    const int l8  = lane & 7;
    const int lhi = (lane >> 3) & 1;
    const int lq  = (lane >> 4) & 1;
    // A x4: m0 rows, m1 rows+8, m2 rows col+16B, m3 rows+8 col+16B
    const uint32_t laneA = (uint32_t)((warpM + l8 + lhi * 8) * PITCH) * 4u + lq * 16u;
    // B x4 (pairs ni, ni+1): m0 rows n0, m1 n0 col+16B, m2 n0+8, m3 n0+8 col+16B
    const uint32_t laneB = (uint32_t)((A_FLOATS + (warpN + l8 + lq * 8) * PITCH)) * 4u
                           + lhi * 16u;

    float acc[4][4][4];
    #pragma unroll
    for (int i = 0; i < 4; i++)
        #pragma unroll
        for (int j = 0; j < 4; j++)
            #pragma unroll
            for (int q = 0; q < 4; q++) acc[i][j][q] = 0.f;

    const int KT = K / BK;

    // stage loader
    auto load_stage = [&](int s, int k0) {
        const float* Ab = A + (size_t)(bm + lrow) * K + k0;
        const float* Bb = B + (size_t)(bn + lrow) * K + k0;
        uint32_t sa = sAu + (s * STAGE_FLOATS + lrow * PITCH) * 4;
        uint32_t sb = sa + A_FLOATS * 4;
        #pragma unroll
        for (int q = 0; q < 2; q++) {
            const int c4 = lc0 + q;
            cp_async16(sa + (c4 * 4) * 4,        Ab + c4 * 4);
            cp_async16(sa + ((c4 + 4) * 4) * 4,  Ab + (c4 + 4) * 4);
            cp_async16(sb + (c4 * 4) * 4,        Bb + c4 * 4);
            cp_async16(sb + ((c4 + 4) * 4) * 4,  Bb + (c4 + 4) * 4);
        }
        cp_commit();
    };

    // prologue: stages 0, 1
    load_stage(0, 0);
    load_stage(1, BK);

    int stage = 0;
    for (int it = 0; it < KT; it++) {
        if (it + 1 < KT) cp_wait1(); else cp_wait0();
        __syncthreads();

        if (it + 2 < KT) {
            int ns = stage + 2; if (ns >= NSTAGE) ns -= NSTAGE;
            load_stage(ns, (it + 2) * BK);
        }

        const uint32_t stg = sAu + stage * (STAGE_FLOATS * 4);

        #pragma unroll
        for (int ks = 0; ks < 4; ks++) {
            uint32_t af[4][4];
            #pragma unroll
            for (int mi = 0; mi < 4; mi++)
                ldsm_x4(af[mi], stg + laneA + mi * (16 * PITCH * 4) + ks * 32);
            uint32_t bf[4][2];
            #pragma unroll
            for (int np = 0; np < 2; np++) {
                uint32_t bq[4];
                ldsm_x4(bq, stg + laneB + np * (16 * PITCH * 4) + ks * 32);
                bf[np * 2][0]     = bq[0];
                bf[np * 2][1]     = bq[1];
                bf[np * 2 + 1][0] = bq[2];
                bf[np * 2 + 1][1] = bq[3];
            }
            #pragma unroll
            for (int mi = 0; mi < 4; mi++)
                #pragma unroll
                for (int ni = 0; ni < 4; ni++)
                    mma_tf32(acc[mi][ni][0], acc[mi][ni][1],
                             acc[mi][ni][2], acc[mi][ni][3],
                             af[mi][0], af[mi][1], af[mi][2], af[mi][3],
                             bf[ni][0], bf[ni][1]);
        }

        stage++; if (stage >= NSTAGE) stage = 0;
    }

    const int r4 = lane >> 2;
    const int q4 = lane & 3;
    #pragma unroll
    for (int mi = 0; mi < 4; mi++) {
        #pragma unroll
        for (int ni = 0; ni < 4; ni++) {
            const int row = bm + warpM + mi * 16 + r4;
            const int col = bn + warpN + ni * 8 + q4 * 2;
            float2 v0 = make_float2(acc[mi][ni][0], acc[mi][ni][1]);
            float2 v1 = make_float2(acc[mi][ni][2], acc[mi][ni][3]);
            *(float2*)(C + (size_t)row * N + col)       = v0;
            *(float2*)(C + (size_t)(row + 8) * N + col) = v1;
        }
    }
}

// ============================================================================
// Bi-directional WKV scan. Emits cat pre-rounded to tf32 for GEMM2.
// ============================================================================
__global__ __launch_bounds__(1024)
void wkv_scan(const float* __restrict__ rkv,
              const float* __restrict__ td,  const float* __restrict__ tf,
              const float* __restrict__ tdr, const float* __restrict__ tfr,
              float* __restrict__ cat)
{
    __shared__ float sA[32 * 33];
    __shared__ float sM[32 * 33];
    __shared__ float sN[32 * 33];
    __shared__ float sD[32 * 33];

    const int cx  = threadIdx.x & 31;
    const int j   = threadIdx.x >> 5;
    const int c   = blockIdx.x * 32 + cx;
    const int b   = blockIdx.y;
    const int dir = blockIdx.z;

    const float w = -__expf(dir ? tdr[c] : td[c]);
    const float u =          dir ? tfr[c] : tf[c];

    const int koff = (dir ? 4 * CDIM : 1 * CDIM) + c;
    const int voff = koff + CDIM;
    const int roff = (dir ? 3 * CDIM : 0) + c;

    const float* base = rkv + (size_t)(b * TDIM) * D6;

    const int tbase = dir ? (TDIM - 1 - j * CHUNK) : (j * CHUNK);
    const int tstep = dir ? -1 : 1;

    float num = 0.f, den = 0.f, mx = -1e38f;
    #pragma unroll 4
    for (int i = 0; i < CHUNK; i++) {
        const size_t row = (size_t)(tbase + tstep * i) * D6;
        const float k = base[row + koff];
        const float v = base[row + voff];
        const float mw = mx + w;
        const float mn = fmaxf(mw, k);
        const float e1 = __expf(mw - mn);
        const float e2 = __expf(k  - mn);
        num = e1 * num + e2 * v;
        den = e1 * den + e2;
        mx  = mn;
    }

    sA[j * 33 + cx] = (float)CHUNK * w;
    sM[j * 33 + cx] = mx;
    sN[j * 33 + cx] = num;
    sD[j * 33 + cx] = den;
    __syncthreads();

    {
        const int cl = cx;
        const int ch = j;
        float a  = sA[cl * 33 + ch];
        float m  = sM[cl * 33 + ch];
        float pn = sN[cl * 33 + ch];
        float pd = sD[cl * 33 + ch];

        #pragma unroll
        for (int off = 1; off < 32; off <<= 1) {
            const float a2  = __shfl_up_sync(0xFFFFFFFFu, a,  off);
            const float m2  = __shfl_up_sync(0xFFFFFFFFu, m,  off);
            const float pn2 = __shfl_up_sync(0xFFFFFFFFu, pn, off);
            const float pd2 = __shfl_up_sync(0xFFFFFFFFu, pd, off);
            if (cl >= off) {
                const float mm = fmaxf(m2 + a, m);
                const float s1 = __expf(m2 + a - mm);
                const float s2 = __expf(m     - mm);
                pn = s1 * pn2 + s2 * pn;
                pd = s1 * pd2 + s2 * pd;
                m  = mm;
                a  = a + a2;
            }
        }
        float pm  = __shfl_up_sync(0xFFFFFFFFu, m,  1);
        float ppn = __shfl_up_sync(0xFFFFFFFFu, pn, 1);
        float ppd = __shfl_up_sync(0xFFFFFFFFu, pd, 1);
        if (cl == 0) { pm = -1e38f; ppn = 0.f; ppd = 0.f; }
        sM[cl * 33 + ch] = pm;
        sN[cl * 33 + ch] = ppn;
        sD[cl * 33 + ch] = ppd;
    }
    __syncthreads();

    mx  = sM[j * 33 + cx];
    num = sN[j * 33 + cx];
    den = sD[j * 33 + cx];

    const int dcol = dir * CDIM + c;
    #pragma unroll 2
    for (int i = 0; i < CHUNK; i++) {
        const int t = tbase + tstep * i;
        const size_t row = (size_t)t * D6;
        const float k = base[row + koff];
        const float v = base[row + voff];
        const float r = base[row + roff];

        const float ku = k + u;
        const float m1 = fmaxf(mx, ku);
        const float e1 = __expf(mx - m1);
        const float e2 = __expf(ku - m1);
        const float y  = (e1 * num + e2 * v) / (e1 * den + e2);
        const float sg = 1.f / (1.f + __expf(-r));

        cat[(size_t)(b * TDIM + t) * D2 + dcol] =
            __uint_as_float(to_tf32(y * sg));

        const float mw  = mx + w;
        const float mn  = fmaxf(mw, k);
        const float e1s = __expf(mw - mn);
        const float e2s = __expf(k  - mn);
        num = e1s * num + e2s * v;
        den = e1s * den + e2s;
        mx  = mn;
    }
}

// ============================================================================
extern "C" void kernel_launch(void* const* d_in, const int* in_sizes, int n_in,
                              void* d_out, int out_size)
{
    const float* x     = (const float*)d_in[0];   // [B,T,C]
    const float* rkv_w = (const float*)d_in[1];   // [6C, C]
    const float* out_w = (const float*)d_in[2];   // [C, 2C]
    const float* td    = (const float*)d_in[3];
    const float* tf    = (const float*)d_in[4];
    const float* tdr   = (const float*)d_in[5];
    const float* tfr   = (const float*)d_in[6];
    float* out = (float*)d_out;                   // [B,T,C]

    float *rkv, *cat, *xc, *w1, *w2;
    cudaGetSymbolAddress((void**)&rkv, g_rkv);
    cudaGetSymbolAddress((void**)&cat, g_cat);
    cudaGetSymbolAddress((void**)&xc,  g_xc);
    cudaGetSymbolAddress((void**)&w1,  g_w1);
    cudaGetSymbolAddress((void**)&w2,  g_w2);

    cudaFuncSetAttribute(gemm_mma, cudaFuncAttributeMaxDynamicSharedMemorySize,
                         GT_SMEM_BYTES);

    // Pre-round inputs to tf32 (RNA)
    {
        const int nx = MROWS * CDIM / 4, n1 = D6 * CDIM / 4, n2 = CDIM * D2 / 4;
        round_tf32_kernel<<<(nx + 255) / 256, 256>>>(x,     xc, nx);
        round_tf32_kernel<<<(n1 + 255) / 256, 256>>>(rkv_w, w1, n1);
        round_tf32_kernel<<<(n2 + 255) / 256, 256>>>(out_w, w2, n2);
    }

    // GEMM1: rkv[8192,6144] = xc @ w1^T
    {
        dim3 grid(D6 / BN, MROWS / BM);   // (48, 64)
        gemm_mma<<<grid, 256, GT_SMEM_BYTES>>>(xc, w1, rkv, MROWS, D6, CDIM);
    }

    // Bi-directional WKV scan + gating -> cat[8192, 2048] (tf32-rounded)
    {
        dim3 grid(CDIM / 32, BDIM, 2);
        wkv_scan<<<grid, 1024>>>(rkv, td, tf, tdr, tfr, cat);
    }

    // GEMM2: out[8192,1024] = cat @ w2^T
    {
        dim3 grid(CDIM / BN, MROWS / BM); // (8, 64)
        gemm_mma<<<grid, 256, GT_SMEM_BYTES>>>(cat, w2, out, MROWS, CDIM, D2);
    }
}

// round 7
// speedup vs baseline: 4.6294x; 1.6973x over previous
#include <cuda_runtime.h>
#include <cuda_fp16.h>
#include <cstdint>

#define BDIM 4
#define TDIM 2048
#define CDIM 1024
#define D6   (6 * CDIM)          // 6144
#define D2   (2 * CDIM)          // 2048
#define MROWS (BDIM * TDIM)      // 8192
#define CHUNK 64                 // T / 32 warps (scan)

// Scratch (allocation-free rule: __device__ globals)
__device__ float  g_rkv[(size_t)MROWS * D6];   // [B*T, 6C] fp32
__device__ __half g_cat[(size_t)MROWS * D2];   // [B*T, 2C] fp16
__device__ __half g_xc [(size_t)MROWS * CDIM]; // x -> fp16
__device__ __half g_w1 [(size_t)D6 * CDIM];    // rkv_w -> fp16
__device__ __half g_w2 [(size_t)CDIM * D2];    // out_w -> fp16

__device__ __forceinline__ uint32_t smem_u32(const void* p) {
    uint32_t a;
    asm("{ .reg .u64 t; cvta.to.shared.u64 t, %1; cvt.u32.u64 %0, t; }"
        : "=r"(a) : "l"(p));
    return a;
}
__device__ __forceinline__ void cp_async16(uint32_t dst, const void* src) {
    asm volatile("cp.async.cg.shared.global [%0], [%1], 16;"
                 :: "r"(dst), "l"(src) : "memory");
}
__device__ __forceinline__ void cp_commit() {
    asm volatile("cp.async.commit_group;" ::: "memory");
}
__device__ __forceinline__ void cp_wait1() {
    asm volatile("cp.async.wait_group 1;" ::: "memory");
}
__device__ __forceinline__ void cp_wait0() {
    asm volatile("cp.async.wait_group 0;" ::: "memory");
}
__device__ __forceinline__ void mma_f16(
    float& c0, float& c1, float& c2, float& c3,
    uint32_t a0, uint32_t a1, uint32_t a2, uint32_t a3,
    uint32_t b0, uint32_t b1)
{
    asm volatile(
        "mma.sync.aligned.m16n8k16.row.col.f32.f16.f16.f32 "
        "{%0,%1,%2,%3}, {%4,%5,%6,%7}, {%8,%9}, {%0,%1,%2,%3};"
        : "+f"(c0), "+f"(c1), "+f"(c2), "+f"(c3)
        : "r"(a0), "r"(a1), "r"(a2), "r"(a3), "r"(b0), "r"(b1));
}
__device__ __forceinline__ void ldsm_x4(uint32_t* r, uint32_t addr) {
    asm volatile("ldmatrix.sync.aligned.m8n8.x4.shared.b16 {%0,%1,%2,%3}, [%4];"
                 : "=r"(r[0]), "=r"(r[1]), "=r"(r[2]), "=r"(r[3]) : "r"(addr));
}

// ============================================================================
// Pre-pass: fp32 -> fp16 (RN). n4 = n/4.
// ============================================================================
__global__ void round_f16_kernel(const float* __restrict__ in,
                                 __half* __restrict__ out, int n4)
{
    int i = blockIdx.x * blockDim.x + threadIdx.x;
    if (i < n4) {
        float4 v = ((const float4*)in)[i];
        __half2 h0 = __floats2half2_rn(v.x, v.y);
        __half2 h1 = __floats2half2_rn(v.z, v.w);
        ((__half2*)out)[i * 2]     = h0;
        ((__half2*)out)[i * 2 + 1] = h1;
    }
}

// ============================================================================
// FP16 mma.sync GEMM (NT): C[M,N](f32) = A[M,K](f16) * B[N,K](f16)^T.
// BM=128, BN=128, BK=32; 256 thr = 8 warps (2M x 4N), warp tile 64x32,
// mma.m16n8k16, ldmatrix fragments, 3-stage cp.async ring (wait_group 1).
// ============================================================================
#define BM 128
#define BN 128
#define BK 32
#define NSTAGE 3
#define PITCH_H 40                            // halfs per smem row (80 B)
#define A_HALFS (BM * PITCH_H)                // 5120
#define B_HALFS (BN * PITCH_H)                // 5120
#define STAGE_HALFS (A_HALFS + B_HALFS)       // 10240
#define GT_SMEM_BYTES (NSTAGE * STAGE_HALFS * 2)   // 61440

__global__ __launch_bounds__(256, 2)
void gemm_mma(const __half* __restrict__ A, const __half* __restrict__ B,
              float* __restrict__ C, int M, int N, int K)
{
    extern __shared__ __half sm[];

    const int tid  = threadIdx.x;
    const int wid  = tid >> 5;
    const int lane = tid & 31;
    const int bm   = blockIdx.y * BM;
    const int bn   = blockIdx.x * BN;

    const int warpM = (wid >> 2) * 64;    // 0 or 64
    const int warpN = (wid & 3) * 32;     // 0..96

    const int lrow = tid >> 1;            // loader row 0..127
    const int lc0  = (tid & 1) * 2;       // 16B-chunk base (0 or 2)

    const uint32_t sAu = smem_u32(sm);

    // ldmatrix lane addressing (byte offsets inside a stage)
    const int l8  = lane & 7;
    const int lhi = (lane >> 3) & 1;
    const int lq  = (lane >> 4) & 1;
    // A x4: m0 rows k0-7, m1 rows+8 k0-7, m2 rows k8-15, m3 rows+8 k8-15
    const uint32_t laneA = (uint32_t)((warpM + l8 + lhi * 8) * PITCH_H) * 2u
                           + lq * 16u;
    // B x4 (ni pair): m0 n k0-7, m1 n k8-15, m2 n+8 k0-7, m3 n+8 k8-15
    const uint32_t laneB = (uint32_t)((A_HALFS + (warpN + l8 + lq * 8) * PITCH_H)) * 2u
                           + lhi * 16u;

    float acc[4][4][4];
    #pragma unroll
    for (int i = 0; i < 4; i++)
        #pragma unroll
        for (int j = 0; j < 4; j++)
            #pragma unroll
            for (int q = 0; q < 4; q++) acc[i][j][q] = 0.f;

    const int KT = K / BK;

    auto load_stage = [&](int s, int k0) {
        const __half* Ab = A + (size_t)(bm + lrow) * K + k0;
        const __half* Bb = B + (size_t)(bn + lrow) * K + k0;
        uint32_t sa = sAu + (s * STAGE_HALFS + lrow * PITCH_H) * 2;
        uint32_t sb = sa + A_HALFS * 2;
        #pragma unroll
        for (int q = 0; q < 2; q++) {
            const int c16 = lc0 + q;          // 0..3 (16B chunks, 8 halfs)
            cp_async16(sa + c16 * 16, Ab + c16 * 8);
            cp_async16(sb + c16 * 16, Bb + c16 * 8);
        }
        cp_commit();
    };

    load_stage(0, 0);
    load_stage(1, BK);

    int stage = 0;
    for (int it = 0; it < KT; it++) {
        if (it + 1 < KT) cp_wait1(); else cp_wait0();
        __syncthreads();

        if (it + 2 < KT) {
            int ns = stage + 2; if (ns >= NSTAGE) ns -= NSTAGE;
            load_stage(ns, (it + 2) * BK);
        }

        const uint32_t stg = sAu + stage * (STAGE_HALFS * 2);

        #pragma unroll
        for (int ks = 0; ks < BK / 16; ks++) {       // 2 slabs of k16
            uint32_t af[4][4];
            #pragma unroll
            for (int mi = 0; mi < 4; mi++)
                ldsm_x4(af[mi], stg + laneA + mi * (16 * PITCH_H * 2) + ks * 32);
            uint32_t bf[4][2];
            #pragma unroll
            for (int np = 0; np < 2; np++) {
                uint32_t bq[4];
                ldsm_x4(bq, stg + laneB + np * (16 * PITCH_H * 2) + ks * 32);
                bf[np * 2][0]     = bq[0];
                bf[np * 2][1]     = bq[1];
                bf[np * 2 + 1][0] = bq[2];
                bf[np * 2 + 1][1] = bq[3];
            }
            #pragma unroll
            for (int mi = 0; mi < 4; mi++)
                #pragma unroll
                for (int ni = 0; ni < 4; ni++)
                    mma_f16(acc[mi][ni][0], acc[mi][ni][1],
                            acc[mi][ni][2], acc[mi][ni][3],
                            af[mi][0], af[mi][1], af[mi][2], af[mi][3],
                            bf[ni][0], bf[ni][1]);
        }

        stage++; if (stage >= NSTAGE) stage = 0;
    }

    const int r4 = lane >> 2;
    const int q4 = lane & 3;
    #pragma unroll
    for (int mi = 0; mi < 4; mi++) {
        #pragma unroll
        for (int ni = 0; ni < 4; ni++) {
            const int row = bm + warpM + mi * 16 + r4;
            const int col = bn + warpN + ni * 8 + q4 * 2;
            float2 v0 = make_float2(acc[mi][ni][0], acc[mi][ni][1]);
            float2 v1 = make_float2(acc[mi][ni][2], acc[mi][ni][3]);
            *(float2*)(C + (size_t)row * N + col)       = v0;
            *(float2*)(C + (size_t)(row + 8) * N + col) = v1;
        }
    }
}

// ============================================================================
// Bi-directional WKV scan (fp32 internal). Emits cat as fp16 for GEMM2.
// ============================================================================
__global__ __launch_bounds__(1024)
void wkv_scan(const float* __restrict__ rkv,
              const float* __restrict__ td,  const float* __restrict__ tf,
              const float* __restrict__ tdr, const float* __restrict__ tfr,
              __half* __restrict__ cat)
{
    __shared__ float sA[32 * 33];
    __shared__ float sM[32 * 33];
    __shared__ float sN[32 * 33];
    __shared__ float sD[32 * 33];

    const int cx  = threadIdx.x & 31;
    const int j   = threadIdx.x >> 5;
    const int c   = blockIdx.x * 32 + cx;
    const int b   = blockIdx.y;
    const int dir = blockIdx.z;

    const float w = -__expf(dir ? tdr[c] : td[c]);
    const float u =          dir ? tfr[c] : tf[c];

    const int koff = (dir ? 4 * CDIM : 1 * CDIM) + c;
    const int voff = koff + CDIM;
    const int roff = (dir ? 3 * CDIM : 0) + c;

    const float* base = rkv + (size_t)(b * TDIM) * D6;

    const int tbase = dir ? (TDIM - 1 - j * CHUNK) : (j * CHUNK);
    const int tstep = dir ? -1 : 1;

    float num = 0.f, den = 0.f, mx = -1e38f;
    #pragma unroll 4
    for (int i = 0; i < CHUNK; i++) {
        const size_t row = (size_t)(tbase + tstep * i) * D6;
        const float k = base[row + koff];
        const float v = base[row + voff];
        const float mw = mx + w;
        const float mn = fmaxf(mw, k);
        const float e1 = __expf(mw - mn);
        const float e2 = __expf(k  - mn);
        num = e1 * num + e2 * v;
        den = e1 * den + e2;
        mx  = mn;
    }

    sA[j * 33 + cx] = (float)CHUNK * w;
    sM[j * 33 + cx] = mx;
    sN[j * 33 + cx] = num;
    sD[j * 33 + cx] = den;
    __syncthreads();

    {
        const int cl = cx;
        const int ch = j;
        float a  = sA[cl * 33 + ch];
        float m  = sM[cl * 33 + ch];
        float pn = sN[cl * 33 + ch];
        float pd = sD[cl * 33 + ch];

        #pragma unroll
        for (int off = 1; off < 32; off <<= 1) {
            const float a2  = __shfl_up_sync(0xFFFFFFFFu, a,  off);
            const float m2  = __shfl_up_sync(0xFFFFFFFFu, m,  off);
            const float pn2 = __shfl_up_sync(0xFFFFFFFFu, pn, off);
            const float pd2 = __shfl_up_sync(0xFFFFFFFFu, pd, off);
            if (cl >= off) {
                const float mm = fmaxf(m2 + a, m);
                const float s1 = __expf(m2 + a - mm);
                const float s2 = __expf(m     - mm);
                pn = s1 * pn2 + s2 * pn;
                pd = s1 * pd2 + s2 * pd;
                m  = mm;
                a  = a + a2;
            }
        }
        float pm  = __shfl_up_sync(0xFFFFFFFFu, m,  1);
        float ppn = __shfl_up_sync(0xFFFFFFFFu, pn, 1);
        float ppd = __shfl_up_sync(0xFFFFFFFFu, pd, 1);
        if (cl == 0) { pm = -1e38f; ppn = 0.f; ppd = 0.f; }
        sM[cl * 33 + ch] = pm;
        sN[cl * 33 + ch] = ppn;
        sD[cl * 33 + ch] = ppd;
    }
    __syncthreads();

    mx  = sM[j * 33 + cx];
    num = sN[j * 33 + cx];
    den = sD[j * 33 + cx];

    const int dcol = dir * CDIM + c;
    #pragma unroll 2
    for (int i = 0; i < CHUNK; i++) {
        const int t = tbase + tstep * i;
        const size_t row = (size_t)t * D6;
        const float k = base[row + koff];
        const float v = base[row + voff];
        const float r = base[row + roff];

        const float ku = k + u;
        const float m1 = fmaxf(mx, ku);
        const float e1 = __expf(mx - m1);
        const float e2 = __expf(ku - m1);
        const float y  = (e1 * num + e2 * v) / (e1 * den + e2);
        const float sg = 1.f / (1.f + __expf(-r));

        cat[(size_t)(b * TDIM + t) * D2 + dcol] = __float2half_rn(y * sg);

        const float mw  = mx + w;
        const float mn  = fmaxf(mw, k);
        const float e1s = __expf(mw - mn);
        const float e2s = __expf(k  - mn);
        num = e1s * num + e2s * v;
        den = e1s * den + e2s;
        mx  = mn;
    }
}

// ============================================================================
extern "C" void kernel_launch(void* const* d_in, const int* in_sizes, int n_in,
                              void* d_out, int out_size)
{
    const float* x     = (const float*)d_in[0];   // [B,T,C]
    const float* rkv_w = (const float*)d_in[1];   // [6C, C]
    const float* out_w = (const float*)d_in[2];   // [C, 2C]
    const float* td    = (const float*)d_in[3];
    const float* tf    = (const float*)d_in[4];
    const float* tdr   = (const float*)d_in[5];
    const float* tfr   = (const float*)d_in[6];
    float* out = (float*)d_out;                   // [B,T,C]

    float* rkv;
    __half *cat, *xc, *w1, *w2;
    cudaGetSymbolAddress((void**)&rkv, g_rkv);
    cudaGetSymbolAddress((void**)&cat, g_cat);
    cudaGetSymbolAddress((void**)&xc,  g_xc);
    cudaGetSymbolAddress((void**)&w1,  g_w1);
    cudaGetSymbolAddress((void**)&w2,  g_w2);

    cudaFuncSetAttribute(gemm_mma, cudaFuncAttributeMaxDynamicSharedMemorySize,
                         GT_SMEM_BYTES);

    // Pre-round inputs to fp16 (RN)
    {
        const int nx = MROWS * CDIM / 4, n1 = D6 * CDIM / 4, n2 = CDIM * D2 / 4;
        round_f16_kernel<<<(nx + 255) / 256, 256>>>(x,     xc, nx);
        round_f16_kernel<<<(n1 + 255) / 256, 256>>>(rkv_w, w1, n1);
        round_f16_kernel<<<(n2 + 255) / 256, 256>>>(out_w, w2, n2);
    }

    // GEMM1: rkv[8192,6144] = xc @ w1^T
    {
        dim3 grid(D6 / BN, MROWS / BM);   // (48, 64)
        gemm_mma<<<grid, 256, GT_SMEM_BYTES>>>(xc, w1, rkv, MROWS, D6, CDIM);
    }

    // Bi-directional WKV scan + gating -> cat[8192, 2048] (fp16)
    {
        dim3 grid(CDIM / 32, BDIM, 2);
        wkv_scan<<<grid, 1024>>>(rkv, td, tf, tdr, tfr, cat);
    }

    // GEMM2: out[8192,1024] = cat @ w2^T
    {
        dim3 grid(CDIM / BN, MROWS / BM); // (8, 64)
        gemm_mma<<<grid, 256, GT_SMEM_BYTES>>>(cat, w2, out, MROWS, CDIM, D2);
    }
}